// round 11
// baseline (speedup 1.0000x reference)
#include <cuda_runtime.h>
#include <cuda_bf16.h>
#include <cstdint>
#include <math.h>

// Problem constants
#define Bq   4
#define Tq   4096
#define Hh   8
#define Dd   32
#define HIDq 512
#define NC   1040            // packed projection columns: q256 k256 v256 w256 beta8 g8
#define NBIG 1024            // tensor-core GEMM1 columns (q,k,v,w)
#define MROWS (Bq*Tq)        // 16384
#define BH   (Bq*Hh)         // 32
#define CCH  64              // chunks
#define LCH  64              // steps per chunk
#define WPB  4               // warps per block in scan kernels

// -------------------- scratch (device globals; zero-initialized, no allocation) ----
__device__ float          g_Y[(size_t)MROWS * NC];        // projection output (68 MB)
__device__ __nv_bfloat16  g_Wh[(size_t)NBIG * HIDq];      // packed weights hi
__device__ __nv_bfloat16  g_Wl[(size_t)NBIG * HIDq];      // packed weights lo
__device__ __nv_bfloat16  g_xh[(size_t)MROWS * HIDq];     // x hi (16 MB)
__device__ __nv_bfloat16  g_xl[(size_t)MROWS * HIDq];     // x lo
__device__ __nv_bfloat16  g_woh[(size_t)HIDq * 256];      // Wo hi
__device__ __nv_bfloat16  g_wol[(size_t)HIDq * 256];      // Wo lo
__device__ __nv_bfloat16  g_atth[(size_t)MROWS * 256];    // attention out hi (8 MB)
__device__ __nv_bfloat16  g_attl[(size_t)MROWS * 256];    // attention out lo
__device__ float4 g_s4[(size_t)BH * Tq * Dd];             // (w, v, k, q*scale*eg) (67 MB)
__device__ float  g_beta[(size_t)BH * Tq];                // beta
__device__ float  g_P [(size_t)BH * CCH * 1024];          // chunk transfer matrices
__device__ float  g_A [(size_t)BH * CCH * 1024];          // chunk injections
__device__ float  g_S0[(size_t)BH * CCH * 1024];          // state at chunk starts

// -------------------- helpers --------------------
__device__ __forceinline__ void bf16split(float v, __nv_bfloat16& hi, __nv_bfloat16& lo) {
    hi = __float2bfloat16(v);
    lo = __float2bfloat16(v - __bfloat162float(hi));
}

__device__ __forceinline__ void ldsm4(uint32_t& r0, uint32_t& r1, uint32_t& r2, uint32_t& r3,
                                      uint32_t addr) {
    asm volatile("ldmatrix.sync.aligned.m8n8.x4.shared.b16 {%0,%1,%2,%3}, [%4];"
        : "=r"(r0), "=r"(r1), "=r"(r2), "=r"(r3) : "r"(addr));
}

__device__ __forceinline__ void mma_bf16(float* d, uint32_t a0, uint32_t a1, uint32_t a2,
                                         uint32_t a3, uint32_t b0, uint32_t b1) {
    asm volatile("mma.sync.aligned.m16n8k16.row.col.f32.bf16.bf16.f32 "
        "{%0,%1,%2,%3}, {%4,%5,%6,%7}, {%8,%9}, {%0,%1,%2,%3};"
        : "+f"(d[0]), "+f"(d[1]), "+f"(d[2]), "+f"(d[3])
        : "r"(a0), "r"(a1), "r"(a2), "r"(a3), "r"(b0), "r"(b1));
}

// swizzled smem byte offset within one 128x32 bf16 array: row stride 64B, 4 chunks of 16B
__device__ __forceinline__ uint32_t swz(int row, int col) {
    uint32_t chunk = (uint32_t)(col >> 3);
    return (uint32_t)(row * 64) + ((chunk ^ (((uint32_t)row >> 1) & 3u)) << 4);
}

// -------------------- fused conversions: weights pack/split, x split, Wo split ------
// blockIdx ranges: [0,2048) packW (1024x512), [2048,10240) cvtA, [10240,10752) cvtWo
__global__ void __launch_bounds__(256) cvtAll(
        const float* __restrict__ x,
        const float* __restrict__ wq, const float* __restrict__ wk,
        const float* __restrict__ wv, const float* __restrict__ ww,
        const float* __restrict__ Wo) {
    int b = blockIdx.x;
    if (b < 2048) {
        int i = b * 256 + threadIdx.x;           // 0 .. 524287
        int r = i >> 9;
        float v;
        if      (r < 256) v = wq[i];
        else if (r < 512) v = wk[i - (256 << 9)];
        else if (r < 768) v = wv[i - (512 << 9)];
        else              v = ww[i - (768 << 9)];
        __nv_bfloat16 hi, lo;
        bf16split(v, hi, lo);
        g_Wh[i] = hi; g_Wl[i] = lo;
    } else if (b < 10240) {
        int i = (b - 2048) * 256 + threadIdx.x;  // float4 index, 2097152 total
        float4 v = ((const float4*)x)[i];
        __nv_bfloat16 h0, l0, h1, l1, h2, l2, h3, l3;
        bf16split(v.x, h0, l0); bf16split(v.y, h1, l1);
        bf16split(v.z, h2, l2); bf16split(v.w, h3, l3);
        ((__nv_bfloat162*)g_xh)[2*i]   = __halves2bfloat162(h0, h1);
        ((__nv_bfloat162*)g_xh)[2*i+1] = __halves2bfloat162(h2, h3);
        ((__nv_bfloat162*)g_xl)[2*i]   = __halves2bfloat162(l0, l1);
        ((__nv_bfloat162*)g_xl)[2*i+1] = __halves2bfloat162(l2, l3);
    } else {
        int i = (b - 10240) * 256 + threadIdx.x; // 0 .. 131071
        __nv_bfloat16 hi, lo;
        bf16split(Wo[i], hi, lo);
        g_woh[i] = hi; g_wol[i] = lo;
    }
}

// -------------------- smallproj: beta/g columns in full fp32 + activations ----------
// one warp per (b,t) row: 16 dots of K=512; writes g_Y cols 1024..1039.
__global__ void __launch_bounds__(256) smallproj(
        const float* __restrict__ x,
        const float* __restrict__ Wb, const float* __restrict__ bb,
        const float* __restrict__ Wg, const float* __restrict__ bg) {
    int row  = blockIdx.x * 8 + (threadIdx.x >> 5);   // 0..16383
    int lane = threadIdx.x & 31;
    const float4* xr = (const float4*)(x + (size_t)row * HIDq) + lane * 4;
    float4 xv0 = xr[0], xv1 = xr[1], xv2 = xr[2], xv3 = xr[3];

    float acc[16];
#pragma unroll
    for (int o = 0; o < 16; ++o) {
        const float* Wrow = (o < 8) ? (Wb + (size_t)o * HIDq) : (Wg + (size_t)(o - 8) * HIDq);
        const float4* wr = (const float4*)Wrow + lane * 4;
        float4 w0 = wr[0], w1 = wr[1], w2 = wr[2], w3 = wr[3];
        float s = 0.f;
        s = fmaf(xv0.x, w0.x, s); s = fmaf(xv0.y, w0.y, s);
        s = fmaf(xv0.z, w0.z, s); s = fmaf(xv0.w, w0.w, s);
        s = fmaf(xv1.x, w1.x, s); s = fmaf(xv1.y, w1.y, s);
        s = fmaf(xv1.z, w1.z, s); s = fmaf(xv1.w, w1.w, s);
        s = fmaf(xv2.x, w2.x, s); s = fmaf(xv2.y, w2.y, s);
        s = fmaf(xv2.z, w2.z, s); s = fmaf(xv2.w, w2.w, s);
        s = fmaf(xv3.x, w3.x, s); s = fmaf(xv3.y, w3.y, s);
        s = fmaf(xv3.z, w3.z, s); s = fmaf(xv3.w, w3.w, s);
        acc[o] = s;
    }
#pragma unroll
    for (int off = 16; off; off >>= 1)
#pragma unroll
        for (int o = 0; o < 16; ++o)
            acc[o] += __shfl_xor_sync(0xffffffffu, acc[o], off);

    if (lane < 16) {
        float v = acc[lane];
        if (lane < 8) v = 2.f / (1.f + expf(-(v + bb[lane])));
        else          v = 1.f / (1.f + expf(-(v + bg[lane - 8])));
        g_Y[(size_t)row * NC + 1024 + lane] = v;
    }
}

// -------------------- tensor-core GEMM: C[M,N] = A[M,K] * B[N,K]^T -------------------
// 3-term bf16 split (AhBh + AhBl + AlBh), fp32 accum. 128x128x32 tiles, 8 warps,
// 64x32 warp tiles. 3-stage cp.async ring (prefetch distance 2), XOR-swizzled 32KB
// stages; 96KB smem -> 2 CTAs/SM. N multiple of 128; C row stride ldC.
__global__ void __launch_bounds__(256, 2)
hgemm3(const __nv_bfloat16* __restrict__ Ahp, const __nv_bfloat16* __restrict__ Alp,
       const __nv_bfloat16* __restrict__ Bhp, const __nv_bfloat16* __restrict__ Blp,
       float* __restrict__ C, int ldC, int K) {
    extern __shared__ __nv_bfloat16 smem[];   // 3 stages * 4 arrays * 128*32 bf16 = 96KB
    const int tid  = threadIdx.x;
    const int wid  = tid >> 5, lane = tid & 31;
    const int m0 = blockIdx.y * 128, n0 = blockIdx.x * 128;
    const int wm = (wid >> 2) * 64, wn = (wid & 3) * 32;
    const uint32_t sbase = (uint32_t)__cvta_generic_to_shared(&smem[0]);

    const __nv_bfloat16* gsrc[4];
    gsrc[0] = Ahp + (size_t)m0 * K;
    gsrc[1] = Alp + (size_t)m0 * K;
    gsrc[2] = Bhp + (size_t)n0 * K;
    gsrc[3] = Blp + (size_t)n0 * K;

    float acc[4][4][4];
#pragma unroll
    for (int mi = 0; mi < 4; ++mi)
#pragma unroll
        for (int nj = 0; nj < 4; ++nj)
#pragma unroll
            for (int cc = 0; cc < 4; ++cc) acc[mi][nj][cc] = 0.f;

    auto load_stage = [&](int s, int kt) {
#pragma unroll
        for (int arr = 0; arr < 4; ++arr) {
            uint32_t abase = sbase + (uint32_t)s * 32768u + (uint32_t)arr * 8192u;
            const __nv_bfloat16* src = gsrc[arr];
#pragma unroll
            for (int i = 0; i < 2; ++i) {
                int lin = i * 256 + tid;         // 0..511 chunk id
                int r = lin >> 2, c = lin & 3;
                uint32_t dst = abase + swz(r, c * 8);
                const void* sp = src + (size_t)r * K + kt + c * 8;
                asm volatile("cp.async.cg.shared.global [%0], [%1], 16;" :: "r"(dst), "l"(sp));
            }
        }
        asm volatile("cp.async.commit_group;");
    };

    const int KT = K / 32;
    load_stage(0, 0);
    if (KT > 1) load_stage(1, 32);

    for (int it = 0; it < KT; ++it) {
        if (it + 2 < KT) {
            load_stage((it + 2) % 3, (it + 2) * 32);
            asm volatile("cp.async.wait_group 2;");
        } else if (it + 1 < KT) {
            asm volatile("cp.async.wait_group 1;");
        } else {
            asm volatile("cp.async.wait_group 0;");
        }
        __syncthreads();

        const uint32_t stg = sbase + (uint32_t)(it % 3) * 32768u;
        const uint32_t aHs = stg;
        const uint32_t aLs = stg + 8192u;
        const uint32_t bHs = stg + 16384u;
        const uint32_t bLs = stg + 24576u;

#pragma unroll
        for (int kk = 0; kk < 32; kk += 16) {
            uint32_t fbh[4][2], fbl[4][2];
#pragma unroll
            for (int j = 0; j < 2; ++j) {
                int row = wn + j * 16 + (lane & 7) + ((lane >> 4) & 1) * 8;
                int col = kk + ((lane >> 3) & 1) * 8;
                uint32_t off = swz(row, col);
                uint32_t t0, t1, t2, t3;
                ldsm4(t0, t1, t2, t3, bHs + off);
                fbh[j*2][0] = t0; fbh[j*2][1] = t1; fbh[j*2+1][0] = t2; fbh[j*2+1][1] = t3;
                ldsm4(t0, t1, t2, t3, bLs + off);
                fbl[j*2][0] = t0; fbl[j*2][1] = t1; fbl[j*2+1][0] = t2; fbl[j*2+1][1] = t3;
            }
#pragma unroll
            for (int mi = 0; mi < 4; ++mi) {
                int row = wm + mi * 16 + (lane & 7) + ((lane >> 3) & 1) * 8;
                int col = kk + ((lane >> 4) & 1) * 8;
                uint32_t off = swz(row, col);
                uint32_t ah0, ah1, ah2, ah3, al0, al1, al2, al3;
                ldsm4(ah0, ah1, ah2, ah3, aHs + off);
                ldsm4(al0, al1, al2, al3, aLs + off);
                // term-major: consecutive MMAs hit distinct accumulators
#pragma unroll
                for (int nj = 0; nj < 4; ++nj)
                    mma_bf16(acc[mi][nj], ah0, ah1, ah2, ah3, fbh[nj][0], fbh[nj][1]);
#pragma unroll
                for (int nj = 0; nj < 4; ++nj)
                    mma_bf16(acc[mi][nj], ah0, ah1, ah2, ah3, fbl[nj][0], fbl[nj][1]);
#pragma unroll
                for (int nj = 0; nj < 4; ++nj)
                    mma_bf16(acc[mi][nj], al0, al1, al2, al3, fbh[nj][0], fbh[nj][1]);
            }
        }
        __syncthreads();
    }

    // epilogue (no guards: N multiple of 128)
    const int grp = lane >> 2, t2c = (lane & 3) << 1;
#pragma unroll
    for (int mi = 0; mi < 4; ++mi) {
#pragma unroll
        for (int nj = 0; nj < 4; ++nj) {
            int gm = m0 + wm + mi * 16 + grp;
            int gn = n0 + wn + nj * 8 + t2c;
            float* p0 = C + (size_t)gm * ldC + gn;
            float* p1 = C + (size_t)(gm + 8) * ldC + gn;
            p0[0] = acc[mi][nj][0]; p0[1] = acc[mi][nj][1];
            p1[0] = acc[mi][nj][2]; p1[1] = acc[mi][nj][3];
        }
    }
}

// -------------------- prep: normalize w, fold q*scale*eg, pack streams --------------------
__global__ void __launch_bounds__(256) prep() {
    const float scale = 0.17677669529663687f;   // 32^-0.5
    int g    = blockIdx.x * 8 + (threadIdx.x >> 5);
    int lane = threadIdx.x & 31;
    int bh = g >> 12;
    int t  = g & 4095;
    int b = bh >> 3, h = bh & 7;
    const float* r = g_Y + (size_t)(b * Tq + t) * NC;

    float w = r[768 + h * 32 + lane];
    float ss = w * w;
    ss += __shfl_xor_sync(0xffffffffu, ss, 16);
    ss += __shfl_xor_sync(0xffffffffu, ss, 8);
    ss += __shfl_xor_sync(0xffffffffu, ss, 4);
    ss += __shfl_xor_sync(0xffffffffu, ss, 2);
    ss += __shfl_xor_sync(0xffffffffu, ss, 1);
    w = w / (sqrtf(ss) + 1e-6f);

    float v    = r[512 + h * 32 + lane];
    float k    = r[256 + h * 32 + lane];
    float q    = r[       h * 32 + lane];
    float beta = r[1024 + h];
    float eg   = r[1032 + h];   // sigmoid(zg) == exp(log_sigmoid(zg))

    g_s4[(size_t)g * 32 + lane] = make_float4(w, v, k, q * scale * eg);
    if (lane == 0) g_beta[g] = beta;
}

// -------------------- pass1: per-chunk transfer matrix P and injection A --------------------
__global__ void __launch_bounds__(WPB*32) scanPA() {
    __shared__ float wbuf[WPB][8][32];
    __shared__ float vbuf[WPB][8][32];
    __shared__ float kbuf[WPB][8][32];
    __shared__ float bbuf[WPB][8];

    const int wid  = threadIdx.x >> 5;
    const int lane = threadIdx.x & 31;
    const int wg   = blockIdx.x * WPB + wid;
    const int bh   = wg >> 6;
    const int c    = wg & 63;
    const size_t sbase = ((size_t)bh * Tq + (size_t)c * LCH) * 32;
    const size_t bbase = (size_t)bh * Tq + (size_t)c * LCH;

    float P[32], A[32];
#pragma unroll
    for (int m = 0; m < 32; ++m) { P[m] = (m == lane) ? 1.f : 0.f; A[m] = 0.f; }

#pragma unroll
    for (int j = 0; j < 8; ++j) {
        float4 r = g_s4[sbase + (size_t)j * 32 + lane];
        wbuf[wid][j][lane] = r.x; vbuf[wid][j][lane] = r.y; kbuf[wid][j][lane] = r.z;
    }
    if (lane < 8) bbuf[wid][lane] = g_beta[bbase + lane];
    __syncwarp();

    for (int t0 = 0; t0 < LCH; t0 += 8) {
        float4 r4[8]; float rb = 0.f;
        const bool more = (t0 + 8) < LCH;
        if (more) {
#pragma unroll
            for (int j = 0; j < 8; ++j)
                r4[j] = g_s4[sbase + (size_t)(t0 + 8 + j) * 32 + lane];
            if (lane < 8) rb = g_beta[bbase + t0 + 8 + lane];
        }
#pragma unroll
        for (int t = 0; t < 8; ++t) {
            const float4* w4p = (const float4*)&wbuf[wid][t][0];
            const float4* v4p = (const float4*)&vbuf[wid][t][0];
            float k    = kbuf[wid][t][lane];
            float beta = bbuf[wid][t];
            float p0 = 0.f, p1 = 0.f, p2 = 0.f, p3 = 0.f;
            float a0 = 0.f, a1 = 0.f, a2 = 0.f, a3 = 0.f;
            float4 w4[8];
#pragma unroll
            for (int j = 0; j < 8; ++j) {
                w4[j] = w4p[j];
                p0 = fmaf(P[4*j+0], w4[j].x, p0);
                p1 = fmaf(P[4*j+1], w4[j].y, p1);
                p2 = fmaf(P[4*j+2], w4[j].z, p2);
                p3 = fmaf(P[4*j+3], w4[j].w, p3);
                a0 = fmaf(A[4*j+0], w4[j].x, a0);
                a1 = fmaf(A[4*j+1], w4[j].y, a1);
                a2 = fmaf(A[4*j+2], w4[j].z, a2);
                a3 = fmaf(A[4*j+3], w4[j].w, a3);
            }
            float cp = -beta * ((p0 + p1) + (p2 + p3));
            float ca = -beta * ((a0 + a1) + (a2 + a3));
#pragma unroll
            for (int j = 0; j < 8; ++j) {
                float4 v4 = v4p[j];
                P[4*j+0] = fmaf(cp, w4[j].x, P[4*j+0]);
                P[4*j+1] = fmaf(cp, w4[j].y, P[4*j+1]);
                P[4*j+2] = fmaf(cp, w4[j].z, P[4*j+2]);
                P[4*j+3] = fmaf(cp, w4[j].w, P[4*j+3]);
                A[4*j+0] = fmaf(ca, w4[j].x, fmaf(k, v4.x, A[4*j+0]));
                A[4*j+1] = fmaf(ca, w4[j].y, fmaf(k, v4.y, A[4*j+1]));
                A[4*j+2] = fmaf(ca, w4[j].z, fmaf(k, v4.z, A[4*j+2]));
                A[4*j+3] = fmaf(ca, w4[j].w, fmaf(k, v4.w, A[4*j+3]));
            }
        }
        __syncwarp();
        if (more) {
#pragma unroll
            for (int j = 0; j < 8; ++j) {
                wbuf[wid][j][lane] = r4[j].x;
                vbuf[wid][j][lane] = r4[j].y;
                kbuf[wid][j][lane] = r4[j].z;
            }
            if (lane < 8) bbuf[wid][lane] = rb;
        }
        __syncwarp();
    }

    size_t obase = ((size_t)bh * CCH + c) * 1024 + (size_t)lane * 32;
#pragma unroll
    for (int j = 0; j < 8; ++j) {
        *(float4*)&g_P[obase + 4*j] = make_float4(P[4*j], P[4*j+1], P[4*j+2], P[4*j+3]);
        *(float4*)&g_A[obase + 4*j] = make_float4(A[4*j], A[4*j+1], A[4*j+2], A[4*j+3]);
    }
}

// -------------------- combine: sequential chunk-boundary states --------------------
__global__ void __launch_bounds__(1024, 1) combine() {
    __shared__ float Ssh[32][32];
    const int bh = blockIdx.x;
    const int tid = threadIdx.x;
    const int d = tid >> 5, m = tid & 31;

    float s = 0.f;
    for (int c = 0; c < CCH; ++c) {
        size_t base = ((size_t)bh * CCH + c) * 1024;
        g_S0[base + tid] = s;
        Ssh[d][m] = s;
        __syncthreads();
        float acc = g_A[base + tid];
        const float* Pc = g_P + base;
#pragma unroll
        for (int mm = 0; mm < 32; ++mm)
            acc = fmaf(Ssh[d][mm], Pc[mm * 32 + m], acc);
        __syncthreads();
        s = acc;
    }
}

// -------------------- pass2: replay chunks, emit outputs as bf16 hi/lo ----------------
__global__ void __launch_bounds__(WPB*32) scanOut() {
    __shared__ float wbuf[WPB][8][32];
    __shared__ float vbuf[WPB][8][32];
    __shared__ float kbuf[WPB][8][32];
    __shared__ float qbuf[WPB][8][32];
    __shared__ float bbuf[WPB][8];
    __shared__ float part[WPB][32][36];

    const int wid  = threadIdx.x >> 5;
    const int lane = threadIdx.x & 31;
    const int wg   = blockIdx.x * WPB + wid;
    const int bh   = wg >> 6;
    const int c    = wg & 63;
    const int b = bh >> 3, h = bh & 7;
    const size_t sbase = ((size_t)bh * Tq + (size_t)c * LCH) * 32;
    const size_t bbase = (size_t)bh * Tq + (size_t)c * LCH;
    const size_t s0base = ((size_t)bh * CCH + c) * 1024 + (size_t)lane * 32;
    const int rowbase = b * Tq + c * LCH;

    float S[32];
#pragma unroll
    for (int j = 0; j < 8; ++j) {
        float4 s0 = *(const float4*)&g_S0[s0base + 4*j];
        S[4*j] = s0.x; S[4*j+1] = s0.y; S[4*j+2] = s0.z; S[4*j+3] = s0.w;
    }

#pragma unroll
    for (int j = 0; j < 8; ++j) {
        float4 r = g_s4[sbase + (size_t)j * 32 + lane];
        wbuf[wid][j][lane] = r.x; vbuf[wid][j][lane] = r.y;
        kbuf[wid][j][lane] = r.z; qbuf[wid][j][lane] = r.w;
    }
    if (lane < 8) bbuf[wid][lane] = g_beta[bbase + lane];
    __syncwarp();

    for (int t0 = 0; t0 < LCH; t0 += 8) {
        float4 r4[8]; float rb = 0.f;
        const bool more = (t0 + 8) < LCH;
        if (more) {
#pragma unroll
            for (int j = 0; j < 8; ++j)
                r4[j] = g_s4[sbase + (size_t)(t0 + 8 + j) * 32 + lane];
            if (lane < 8) rb = g_beta[bbase + t0 + 8 + lane];
        }
#pragma unroll
        for (int t = 0; t < 8; ++t) {
            const float4* w4p = (const float4*)&wbuf[wid][t][0];
            const float4* v4p = (const float4*)&vbuf[wid][t][0];
            float k    = kbuf[wid][t][lane];
            float q    = qbuf[wid][t][lane];
            float beta = bbuf[wid][t];
            float a0 = 0.f, a1 = 0.f, a2 = 0.f, a3 = 0.f;
            float4 w4[8];
#pragma unroll
            for (int j = 0; j < 8; ++j) {
                w4[j] = w4p[j];
                a0 = fmaf(S[4*j+0], w4[j].x, a0);
                a1 = fmaf(S[4*j+1], w4[j].y, a1);
                a2 = fmaf(S[4*j+2], w4[j].z, a2);
                a3 = fmaf(S[4*j+3], w4[j].w, a3);
            }
            float cs = -beta * ((a0 + a1) + (a2 + a3));
#pragma unroll
            for (int j = 0; j < 8; ++j) {
                float4 v4 = v4p[j];
                S[4*j+0] = fmaf(cs, w4[j].x, fmaf(k, v4.x, S[4*j+0]));
                S[4*j+1] = fmaf(cs, w4[j].y, fmaf(k, v4.y, S[4*j+1]));
                S[4*j+2] = fmaf(cs, w4[j].z, fmaf(k, v4.z, S[4*j+2]));
                S[4*j+3] = fmaf(cs, w4[j].w, fmaf(k, v4.w, S[4*j+3]));
            }
#pragma unroll
            for (int j = 0; j < 8; ++j) {
                *(float4*)&part[wid][lane][4*j] =
                    make_float4(q * S[4*j], q * S[4*j+1], q * S[4*j+2], q * S[4*j+3]);
            }
            __syncwarp();
            float o0 = 0.f, o1 = 0.f, o2 = 0.f, o3 = 0.f;
#pragma unroll
            for (int dd = 0; dd < 32; dd += 4) {
                o0 += part[wid][dd+0][lane];
                o1 += part[wid][dd+1][lane];
                o2 += part[wid][dd+2][lane];
                o3 += part[wid][dd+3][lane];
            }
            float o = (o0 + o1) + (o2 + o3);
            size_t oidx = (size_t)(rowbase + t0 + t) * 256 + h * 32 + lane;
            __nv_bfloat16 hi, lo;
            bf16split(o, hi, lo);
            g_atth[oidx] = hi; g_attl[oidx] = lo;
            __syncwarp();
        }
        if (more) {
#pragma unroll
            for (int j = 0; j < 8; ++j) {
                wbuf[wid][j][lane] = r4[j].x;
                vbuf[wid][j][lane] = r4[j].y;
                kbuf[wid][j][lane] = r4[j].z;
                qbuf[wid][j][lane] = r4[j].w;
            }
            if (lane < 8) bbuf[wid][lane] = rb;
        }
        __syncwarp();
    }
}

// -------------------- launch --------------------
extern "C" void kernel_launch(void* const* d_in, const int* in_sizes, int n_in,
                              void* d_out, int out_size) {
    const float* x     = (const float*)d_in[0];
    const float* Wq    = (const float*)d_in[1];
    const float* Wk    = (const float*)d_in[2];
    const float* Wv    = (const float*)d_in[3];
    const float* Ww    = (const float*)d_in[4];
    const float* Wbeta = (const float*)d_in[5];
    const float* bbeta = (const float*)d_in[6];
    const float* Wg    = (const float*)d_in[7];
    const float* bg    = (const float*)d_in[8];
    const float* Wo    = (const float*)d_in[9];
    float* out = (float*)d_out;

    void *pY, *pXh, *pXl, *pWh, *pWl, *pAh, *pAl, *pWoh, *pWol;
    cudaGetSymbolAddress(&pY,   g_Y);
    cudaGetSymbolAddress(&pXh,  g_xh);
    cudaGetSymbolAddress(&pXl,  g_xl);
    cudaGetSymbolAddress(&pWh,  g_Wh);
    cudaGetSymbolAddress(&pWl,  g_Wl);
    cudaGetSymbolAddress(&pAh,  g_atth);
    cudaGetSymbolAddress(&pAl,  g_attl);
    cudaGetSymbolAddress(&pWoh, g_woh);
    cudaGetSymbolAddress(&pWol, g_wol);

    const int SMEM = 3 * 4 * 128 * 32 * 2;   // 98304 bytes (3 swizzled 32KB stages)
    cudaFuncSetAttribute(hgemm3, cudaFuncAttributeMaxDynamicSharedMemorySize, SMEM);

    // 1) fused conversions + beta/g small projection (fp32)
    cvtAll<<<10752, 256>>>(x, Wq, Wk, Wv, Ww, Wo);
    smallproj<<<MROWS / 8, 256>>>(x, Wbeta, bbeta, Wg, bg);

    // 2) projection GEMM: Y[:,0:1024] = x @ W^T (tensor cores, no padding waste)
    hgemm3<<<dim3(NBIG / 128, MROWS / 128), 256, SMEM>>>(
        (const __nv_bfloat16*)pXh, (const __nv_bfloat16*)pXl,
        (const __nv_bfloat16*)pWh, (const __nv_bfloat16*)pWl,
        (float*)pY, NC, HIDq);

    // 3) normalize w, fold scales, pack recurrence streams
    prep<<<16384, 256>>>();

    // 4) chunked associative scan over the recurrence
    scanPA<<<(BH * CCH) / WPB, WPB * 32>>>();
    combine<<<BH, 1024>>>();
    scanOut<<<(BH * CCH) / WPB, WPB * 32>>>();

    // 5) output projection: out[16384,512] = att @ Wo^T (tensor cores)
    hgemm3<<<dim3(HIDq / 128, MROWS / 128), 256, SMEM>>>(
        (const __nv_bfloat16*)pAh, (const __nv_bfloat16*)pAl,
        (const __nv_bfloat16*)pWoh, (const __nv_bfloat16*)pWol,
        out, HIDq, Hh * Dd);
}

// round 12
// speedup vs baseline: 1.1444x; 1.1444x over previous
#include <cuda_runtime.h>
#include <cuda_bf16.h>
#include <cstdint>
#include <math.h>

// Problem constants
#define Bq   4
#define Tq   4096
#define Hh   8
#define Dd   32
#define HIDq 512
#define NC   1040            // packed projection columns: q256 k256 v256 w256 beta8 g8
#define NCP  1152            // NC padded to multiple of 128
#define MROWS (Bq*Tq)        // 16384
#define BH   (Bq*Hh)         // 32
#define CCH  64              // chunks
#define LCH  64              // steps per chunk
#define WPB  4               // warps per block in scan kernels

// -------------------- scratch (device globals; zero-initialized, no allocation) ----
__device__ float          g_Y[(size_t)MROWS * NC];        // projection output (68 MB)
__device__ __nv_bfloat16  g_Wh[(size_t)NCP * HIDq];       // packed weights hi (pad rows zero)
__device__ __nv_bfloat16  g_Wl[(size_t)NCP * HIDq];       // packed weights lo
__device__ __nv_bfloat16  g_xh[(size_t)MROWS * HIDq];     // x hi (16 MB)
__device__ __nv_bfloat16  g_xl[(size_t)MROWS * HIDq];     // x lo
__device__ __nv_bfloat16  g_woh[(size_t)HIDq * 256];      // Wo hi
__device__ __nv_bfloat16  g_wol[(size_t)HIDq * 256];      // Wo lo
__device__ __nv_bfloat16  g_atth[(size_t)MROWS * 256];    // attention out hi (8 MB)
__device__ __nv_bfloat16  g_attl[(size_t)MROWS * 256];    // attention out lo
__device__ float  g_w[(size_t)BH * Tq * Dd];              // normalized w (SoA streams)
__device__ float  g_v[(size_t)BH * Tq * Dd];
__device__ float  g_k[(size_t)BH * Tq * Dd];
__device__ float  g_q[(size_t)BH * Tq * Dd];              // q*scale*eg
__device__ float  g_beta[(size_t)BH * Tq];                // beta
__device__ float  g_P [(size_t)BH * CCH * 1024];          // chunk transfer matrices
__device__ float  g_A [(size_t)BH * CCH * 1024];          // chunk injections
__device__ float  g_S0[(size_t)BH * CCH * 1024];          // state at chunk starts

// -------------------- helpers --------------------
__device__ __forceinline__ void bf16split(float v, __nv_bfloat16& hi, __nv_bfloat16& lo) {
    hi = __float2bfloat16(v);
    lo = __float2bfloat16(v - __bfloat162float(hi));
}

__device__ __forceinline__ void ldsm4(uint32_t& r0, uint32_t& r1, uint32_t& r2, uint32_t& r3,
                                      uint32_t addr) {
    asm volatile("ldmatrix.sync.aligned.m8n8.x4.shared.b16 {%0,%1,%2,%3}, [%4];"
        : "=r"(r0), "=r"(r1), "=r"(r2), "=r"(r3) : "r"(addr));
}

__device__ __forceinline__ void mma_bf16(float* d, uint32_t a0, uint32_t a1, uint32_t a2,
                                         uint32_t a3, uint32_t b0, uint32_t b1) {
    asm volatile("mma.sync.aligned.m16n8k16.row.col.f32.bf16.bf16.f32 "
        "{%0,%1,%2,%3}, {%4,%5,%6,%7}, {%8,%9}, {%0,%1,%2,%3};"
        : "+f"(d[0]), "+f"(d[1]), "+f"(d[2]), "+f"(d[3])
        : "r"(a0), "r"(a1), "r"(a2), "r"(a3), "r"(b0), "r"(b1));
}

// swizzled smem byte offset within one 128x32 bf16 array: row stride 64B, 4 chunks of 16B
__device__ __forceinline__ uint32_t swz(int row, int col) {
    uint32_t chunk = (uint32_t)(col >> 3);
    return (uint32_t)(row * 64) + ((chunk ^ (((uint32_t)row >> 1) & 3u)) << 4);
}

__device__ __forceinline__ uint32_t s2u(const void* p) {
    return (uint32_t)__cvta_generic_to_shared(p);
}

// -------------------- weight packing + bf16 split --------------------
__global__ void packW2(const float* __restrict__ wq, const float* __restrict__ wk,
                       const float* __restrict__ wv, const float* __restrict__ ww,
                       const float* __restrict__ wb, const float* __restrict__ wg) {
    int i = blockIdx.x * 256 + threadIdx.x;
    if (i >= NC * HIDq) return;
    int r = i / HIDq, c = i % HIDq;
    float v;
    if      (r < 256)  v = wq[i];
    else if (r < 512)  v = wk[(r - 256)  * HIDq + c];
    else if (r < 768)  v = wv[(r - 512)  * HIDq + c];
    else if (r < 1024) v = ww[(r - 768)  * HIDq + c];
    else if (r < 1032) v = wb[(r - 1024) * HIDq + c];
    else               v = wg[(r - 1032) * HIDq + c];
    __nv_bfloat16 hi, lo;
    bf16split(v, hi, lo);
    g_Wh[i] = hi; g_Wl[i] = lo;
}

// -------------------- x -> bf16 hi/lo --------------------
__global__ void cvtA(const float* __restrict__ x) {
    int i = blockIdx.x * 256 + threadIdx.x;      // float4 index
    float4 v = ((const float4*)x)[i];
    __nv_bfloat16 h0, l0, h1, l1, h2, l2, h3, l3;
    bf16split(v.x, h0, l0); bf16split(v.y, h1, l1);
    bf16split(v.z, h2, l2); bf16split(v.w, h3, l3);
    ((__nv_bfloat162*)g_xh)[2*i]   = __halves2bfloat162(h0, h1);
    ((__nv_bfloat162*)g_xh)[2*i+1] = __halves2bfloat162(h2, h3);
    ((__nv_bfloat162*)g_xl)[2*i]   = __halves2bfloat162(l0, l1);
    ((__nv_bfloat162*)g_xl)[2*i+1] = __halves2bfloat162(l2, l3);
}

// -------------------- Wo -> bf16 hi/lo --------------------
__global__ void cvtWo(const float* __restrict__ Wo) {
    int i = blockIdx.x * 256 + threadIdx.x;
    if (i >= HIDq * 256) return;
    __nv_bfloat16 hi, lo;
    bf16split(Wo[i], hi, lo);
    g_woh[i] = hi; g_wol[i] = lo;
}

// -------------------- tensor-core GEMM: C[M,Nreal] = A[M,K] * B[N,K]^T --------------
// (identical to R10: 3-term bf16 split, 128x128x32, 8 warps, 64x32 warp tiles,
//  3-stage swizzled cp.async ring, 2 CTAs/SM)
__global__ void __launch_bounds__(256, 2)
hgemm3(const __nv_bfloat16* __restrict__ Ahp, const __nv_bfloat16* __restrict__ Alp,
       const __nv_bfloat16* __restrict__ Bhp, const __nv_bfloat16* __restrict__ Blp,
       float* __restrict__ C, int M, int Nreal, int K, int epi,
       const float* __restrict__ bbeta, const float* __restrict__ bg) {
    extern __shared__ __nv_bfloat16 smem[];   // 3 stages * 4 arrays * 128*32 bf16 = 96KB
    const int tid  = threadIdx.x;
    const int wid  = tid >> 5, lane = tid & 31;
    const int m0 = blockIdx.y * 128, n0 = blockIdx.x * 128;
    const int wm = (wid >> 2) * 64, wn = (wid & 3) * 32;
    const uint32_t sbase = s2u(&smem[0]);

    const __nv_bfloat16* gsrc[4];
    gsrc[0] = Ahp + (size_t)m0 * K;
    gsrc[1] = Alp + (size_t)m0 * K;
    gsrc[2] = Bhp + (size_t)n0 * K;
    gsrc[3] = Blp + (size_t)n0 * K;

    float acc[4][4][4];
#pragma unroll
    for (int mi = 0; mi < 4; ++mi)
#pragma unroll
        for (int nj = 0; nj < 4; ++nj)
#pragma unroll
            for (int cc = 0; cc < 4; ++cc) acc[mi][nj][cc] = 0.f;

    auto load_stage = [&](int s, int kt) {
#pragma unroll
        for (int arr = 0; arr < 4; ++arr) {
            uint32_t abase = sbase + (uint32_t)s * 32768u + (uint32_t)arr * 8192u;
            const __nv_bfloat16* src = gsrc[arr];
#pragma unroll
            for (int i = 0; i < 2; ++i) {
                int lin = i * 256 + tid;
                int r = lin >> 2, c = lin & 3;
                uint32_t dst = abase + swz(r, c * 8);
                const void* sp = src + (size_t)r * K + kt + c * 8;
                asm volatile("cp.async.cg.shared.global [%0], [%1], 16;" :: "r"(dst), "l"(sp));
            }
        }
        asm volatile("cp.async.commit_group;");
    };

    const int KT = K / 32;
    load_stage(0, 0);
    if (KT > 1) load_stage(1, 32);

    for (int it = 0; it < KT; ++it) {
        if (it + 2 < KT) {
            load_stage((it + 2) % 3, (it + 2) * 32);
            asm volatile("cp.async.wait_group 2;");
        } else if (it + 1 < KT) {
            asm volatile("cp.async.wait_group 1;");
        } else {
            asm volatile("cp.async.wait_group 0;");
        }
        __syncthreads();

        const uint32_t stg = sbase + (uint32_t)(it % 3) * 32768u;
        const uint32_t aHs = stg;
        const uint32_t aLs = stg + 8192u;
        const uint32_t bHs = stg + 16384u;
        const uint32_t bLs = stg + 24576u;

#pragma unroll
        for (int kk = 0; kk < 32; kk += 16) {
            uint32_t fbh[4][2], fbl[4][2];
#pragma unroll
            for (int j = 0; j < 2; ++j) {
                int row = wn + j * 16 + (lane & 7) + ((lane >> 4) & 1) * 8;
                int col = kk + ((lane >> 3) & 1) * 8;
                uint32_t off = swz(row, col);
                uint32_t t0, t1, t2, t3;
                ldsm4(t0, t1, t2, t3, bHs + off);
                fbh[j*2][0] = t0; fbh[j*2][1] = t1; fbh[j*2+1][0] = t2; fbh[j*2+1][1] = t3;
                ldsm4(t0, t1, t2, t3, bLs + off);
                fbl[j*2][0] = t0; fbl[j*2][1] = t1; fbl[j*2+1][0] = t2; fbl[j*2+1][1] = t3;
            }
#pragma unroll
            for (int mi = 0; mi < 4; ++mi) {
                int row = wm + mi * 16 + (lane & 7) + ((lane >> 3) & 1) * 8;
                int col = kk + ((lane >> 4) & 1) * 8;
                uint32_t off = swz(row, col);
                uint32_t ah0, ah1, ah2, ah3, al0, al1, al2, al3;
                ldsm4(ah0, ah1, ah2, ah3, aHs + off);
                ldsm4(al0, al1, al2, al3, aLs + off);
#pragma unroll
                for (int nj = 0; nj < 4; ++nj)
                    mma_bf16(acc[mi][nj], ah0, ah1, ah2, ah3, fbh[nj][0], fbh[nj][1]);
#pragma unroll
                for (int nj = 0; nj < 4; ++nj)
                    mma_bf16(acc[mi][nj], ah0, ah1, ah2, ah3, fbl[nj][0], fbl[nj][1]);
#pragma unroll
                for (int nj = 0; nj < 4; ++nj)
                    mma_bf16(acc[mi][nj], al0, al1, al2, al3, fbh[nj][0], fbh[nj][1]);
            }
        }
        __syncthreads();
    }

    const int grp = lane >> 2, t2c = (lane & 3) << 1;
#pragma unroll
    for (int mi = 0; mi < 4; ++mi) {
#pragma unroll
        for (int nj = 0; nj < 4; ++nj) {
            int gm = m0 + wm + mi * 16 + grp;
            int gn = n0 + wn + nj * 8 + t2c;
            if (gn < Nreal) {
                float v0 = acc[mi][nj][0], v1 = acc[mi][nj][1];
                float v2 = acc[mi][nj][2], v3 = acc[mi][nj][3];
                if (epi && gn >= 1024) {
                    if (gn < 1032) {
                        v0 = 2.f / (1.f + expf(-(v0 + bbeta[gn - 1024])));
                        v1 = 2.f / (1.f + expf(-(v1 + bbeta[gn - 1023])));
                        v2 = 2.f / (1.f + expf(-(v2 + bbeta[gn - 1024])));
                        v3 = 2.f / (1.f + expf(-(v3 + bbeta[gn - 1023])));
                    } else {
                        v0 = 1.f / (1.f + expf(-(v0 + bg[gn - 1032])));
                        v1 = 1.f / (1.f + expf(-(v1 + bg[gn - 1031])));
                        v2 = 1.f / (1.f + expf(-(v2 + bg[gn - 1032])));
                        v3 = 1.f / (1.f + expf(-(v3 + bg[gn - 1031])));
                    }
                }
                float* p0 = C + (size_t)gm * Nreal + gn;
                float* p1 = C + (size_t)(gm + 8) * Nreal + gn;
                p0[0] = v0; p0[1] = v1;
                p1[0] = v2; p1[1] = v3;
            }
        }
    }
}

// -------------------- prep: normalize w, fold q*scale*eg, SoA streams ---------------
__global__ void __launch_bounds__(256) prep() {
    const float scale = 0.17677669529663687f;   // 32^-0.5
    int g    = blockIdx.x * 8 + (threadIdx.x >> 5);
    int lane = threadIdx.x & 31;
    int bh = g >> 12;
    int t  = g & 4095;
    int b = bh >> 3, h = bh & 7;
    const float* r = g_Y + (size_t)(b * Tq + t) * NC;

    float w = r[768 + h * 32 + lane];
    float ss = w * w;
    ss += __shfl_xor_sync(0xffffffffu, ss, 16);
    ss += __shfl_xor_sync(0xffffffffu, ss, 8);
    ss += __shfl_xor_sync(0xffffffffu, ss, 4);
    ss += __shfl_xor_sync(0xffffffffu, ss, 2);
    ss += __shfl_xor_sync(0xffffffffu, ss, 1);
    w = w / (sqrtf(ss) + 1e-6f);

    float v    = r[512 + h * 32 + lane];
    float k    = r[256 + h * 32 + lane];
    float q    = r[       h * 32 + lane];
    float beta = r[1024 + h];
    float eg   = r[1032 + h];   // sigmoid(zg) == exp(log_sigmoid(zg))

    size_t o = (size_t)g * 32 + lane;
    g_w[o] = w; g_v[o] = v; g_k[o] = k; g_q[o] = q * scale * eg;
    if (lane == 0) g_beta[g] = beta;
}

// -------------------- pass1: per-chunk transfer matrix P and injection A --------------------
// cp.async double-buffered SoA windows (no register prefetch -> lower reg pressure).
__global__ void __launch_bounds__(WPB*32) scanPA() {
    __shared__ float wbuf[WPB][2][8][32];
    __shared__ float vbuf[WPB][2][8][32];
    __shared__ float kbuf[WPB][2][8][32];
    __shared__ float bbuf[WPB][2][8];

    const int wid  = threadIdx.x >> 5;
    const int lane = threadIdx.x & 31;
    const int wg   = blockIdx.x * WPB + wid;
    const int bh   = wg >> 6;
    const int c    = wg & 63;
    const size_t sbase = ((size_t)bh * Tq + (size_t)c * LCH) * 32;
    const size_t bbase = (size_t)bh * Tq + (size_t)c * LCH;

    auto issue = [&](int wnd, int bf) {
        size_t goff = sbase + (size_t)wnd * 256;
        uint32_t dw = s2u(&wbuf[wid][bf][0][0]);
        uint32_t dv = s2u(&vbuf[wid][bf][0][0]);
        uint32_t dk = s2u(&kbuf[wid][bf][0][0]);
#pragma unroll
        for (int i = 0; i < 2; ++i) {
            int e4 = i * 32 + lane;                 // float4 index within 256-float window
            const void* sw = (const float4*)(g_w + goff) + e4;
            const void* sv = (const float4*)(g_v + goff) + e4;
            const void* sk = (const float4*)(g_k + goff) + e4;
            asm volatile("cp.async.cg.shared.global [%0], [%1], 16;" :: "r"(dw + e4*16u), "l"(sw));
            asm volatile("cp.async.cg.shared.global [%0], [%1], 16;" :: "r"(dv + e4*16u), "l"(sv));
            asm volatile("cp.async.cg.shared.global [%0], [%1], 16;" :: "r"(dk + e4*16u), "l"(sk));
        }
        if (lane < 8) {
            uint32_t db = s2u(&bbuf[wid][bf][lane]);
            asm volatile("cp.async.ca.shared.global [%0], [%1], 4;"
                         :: "r"(db), "l"(g_beta + bbase + wnd * 8 + lane));
        }
        asm volatile("cp.async.commit_group;");
    };

    issue(0, 0);
    issue(1, 1);
    asm volatile("cp.async.wait_group 1;" ::: "memory");
    __syncwarp();

    float P[32], A[32];
#pragma unroll
    for (int m = 0; m < 32; ++m) { P[m] = (m == lane) ? 1.f : 0.f; A[m] = 0.f; }

    for (int w = 0; w < 8; ++w) {
        const int cur = w & 1;
#pragma unroll
        for (int t = 0; t < 8; ++t) {
            const float4* w4p = (const float4*)&wbuf[wid][cur][t][0];
            const float4* v4p = (const float4*)&vbuf[wid][cur][t][0];
            float k    = kbuf[wid][cur][t][lane];
            float beta = bbuf[wid][cur][t];
            float p0 = 0.f, p1 = 0.f, p2 = 0.f, p3 = 0.f;
            float a0 = 0.f, a1 = 0.f, a2 = 0.f, a3 = 0.f;
            float4 w4[8];
#pragma unroll
            for (int j = 0; j < 8; ++j) {
                w4[j] = w4p[j];
                p0 = fmaf(P[4*j+0], w4[j].x, p0);
                p1 = fmaf(P[4*j+1], w4[j].y, p1);
                p2 = fmaf(P[4*j+2], w4[j].z, p2);
                p3 = fmaf(P[4*j+3], w4[j].w, p3);
                a0 = fmaf(A[4*j+0], w4[j].x, a0);
                a1 = fmaf(A[4*j+1], w4[j].y, a1);
                a2 = fmaf(A[4*j+2], w4[j].z, a2);
                a3 = fmaf(A[4*j+3], w4[j].w, a3);
            }
            float cp = -beta * ((p0 + p1) + (p2 + p3));
            float ca = -beta * ((a0 + a1) + (a2 + a3));
#pragma unroll
            for (int j = 0; j < 8; ++j) {
                float4 v4 = v4p[j];
                P[4*j+0] = fmaf(cp, w4[j].x, P[4*j+0]);
                P[4*j+1] = fmaf(cp, w4[j].y, P[4*j+1]);
                P[4*j+2] = fmaf(cp, w4[j].z, P[4*j+2]);
                P[4*j+3] = fmaf(cp, w4[j].w, P[4*j+3]);
                A[4*j+0] = fmaf(ca, w4[j].x, fmaf(k, v4.x, A[4*j+0]));
                A[4*j+1] = fmaf(ca, w4[j].y, fmaf(k, v4.y, A[4*j+1]));
                A[4*j+2] = fmaf(ca, w4[j].z, fmaf(k, v4.z, A[4*j+2]));
                A[4*j+3] = fmaf(ca, w4[j].w, fmaf(k, v4.w, A[4*j+3]));
            }
        }
        if (w < 6) {
            __syncwarp();
            issue(w + 2, cur);
            asm volatile("cp.async.wait_group 1;" ::: "memory");
            __syncwarp();
        } else if (w == 6) {
            asm volatile("cp.async.wait_group 0;" ::: "memory");
            __syncwarp();
        }
    }

    size_t obase = ((size_t)bh * CCH + c) * 1024 + (size_t)lane * 32;
#pragma unroll
    for (int j = 0; j < 8; ++j) {
        *(float4*)&g_P[obase + 4*j] = make_float4(P[4*j], P[4*j+1], P[4*j+2], P[4*j+3]);
        *(float4*)&g_A[obase + 4*j] = make_float4(A[4*j], A[4*j+1], A[4*j+2], A[4*j+3]);
    }
}

// -------------------- combine: sequential chunk-boundary states --------------------
__global__ void __launch_bounds__(1024, 1) combine() {
    __shared__ float Ssh[32][32];
    const int bh = blockIdx.x;
    const int tid = threadIdx.x;
    const int d = tid >> 5, m = tid & 31;

    float s = 0.f;
    for (int c = 0; c < CCH; ++c) {
        size_t base = ((size_t)bh * CCH + c) * 1024;
        g_S0[base + tid] = s;
        Ssh[d][m] = s;
        __syncthreads();
        float acc = g_A[base + tid];
        const float* Pc = g_P + base;
#pragma unroll
        for (int mm = 0; mm < 32; ++mm)
            acc = fmaf(Ssh[d][mm], Pc[mm * 32 + m], acc);
        __syncthreads();
        s = acc;
    }
}

// -------------------- pass2: replay chunks, emit outputs as bf16 hi/lo ----------------
// cp.async double-buffered; dynamic smem (51456 B).
__global__ void __launch_bounds__(WPB*32) scanOut() {
    extern __shared__ float dyn[];
    float (*wbuf)[2][8][32] = (float(*)[2][8][32])(dyn);
    float (*vbuf)[2][8][32] = (float(*)[2][8][32])(dyn + 2048);
    float (*kbuf)[2][8][32] = (float(*)[2][8][32])(dyn + 4096);
    float (*qbuf)[2][8][32] = (float(*)[2][8][32])(dyn + 6144);
    float (*part)[32][36]   = (float(*)[32][36])(dyn + 8192);
    float (*bbuf)[2][8]     = (float(*)[2][8])(dyn + 8192 + WPB*32*36);

    const int wid  = threadIdx.x >> 5;
    const int lane = threadIdx.x & 31;
    const int wg   = blockIdx.x * WPB + wid;
    const int bh   = wg >> 6;
    const int c    = wg & 63;
    const int b = bh >> 3, h = bh & 7;
    const size_t sbase = ((size_t)bh * Tq + (size_t)c * LCH) * 32;
    const size_t bbase = (size_t)bh * Tq + (size_t)c * LCH;
    const size_t s0base = ((size_t)bh * CCH + c) * 1024 + (size_t)lane * 32;
    const int rowbase = b * Tq + c * LCH;

    auto issue = [&](int wnd, int bf) {
        size_t goff = sbase + (size_t)wnd * 256;
        uint32_t dw = s2u(&wbuf[wid][bf][0][0]);
        uint32_t dv = s2u(&vbuf[wid][bf][0][0]);
        uint32_t dk = s2u(&kbuf[wid][bf][0][0]);
        uint32_t dq = s2u(&qbuf[wid][bf][0][0]);
#pragma unroll
        for (int i = 0; i < 2; ++i) {
            int e4 = i * 32 + lane;
            asm volatile("cp.async.cg.shared.global [%0], [%1], 16;"
                         :: "r"(dw + e4*16u), "l"((const float4*)(g_w + goff) + e4));
            asm volatile("cp.async.cg.shared.global [%0], [%1], 16;"
                         :: "r"(dv + e4*16u), "l"((const float4*)(g_v + goff) + e4));
            asm volatile("cp.async.cg.shared.global [%0], [%1], 16;"
                         :: "r"(dk + e4*16u), "l"((const float4*)(g_k + goff) + e4));
            asm volatile("cp.async.cg.shared.global [%0], [%1], 16;"
                         :: "r"(dq + e4*16u), "l"((const float4*)(g_q + goff) + e4));
        }
        if (lane < 8) {
            uint32_t db = s2u(&bbuf[wid][bf][lane]);
            asm volatile("cp.async.ca.shared.global [%0], [%1], 4;"
                         :: "r"(db), "l"(g_beta + bbase + wnd * 8 + lane));
        }
        asm volatile("cp.async.commit_group;");
    };

    issue(0, 0);
    issue(1, 1);
    asm volatile("cp.async.wait_group 1;" ::: "memory");
    __syncwarp();

    float S[32];
#pragma unroll
    for (int j = 0; j < 8; ++j) {
        float4 s0 = *(const float4*)&g_S0[s0base + 4*j];
        S[4*j] = s0.x; S[4*j+1] = s0.y; S[4*j+2] = s0.z; S[4*j+3] = s0.w;
    }

    for (int w = 0; w < 8; ++w) {
        const int cur = w & 1;
#pragma unroll
        for (int t = 0; t < 8; ++t) {
            const float4* w4p = (const float4*)&wbuf[wid][cur][t][0];
            const float4* v4p = (const float4*)&vbuf[wid][cur][t][0];
            float k    = kbuf[wid][cur][t][lane];
            float q    = qbuf[wid][cur][t][lane];
            float beta = bbuf[wid][cur][t];
            float a0 = 0.f, a1 = 0.f, a2 = 0.f, a3 = 0.f;
            float4 w4[8];
#pragma unroll
            for (int j = 0; j < 8; ++j) {
                w4[j] = w4p[j];
                a0 = fmaf(S[4*j+0], w4[j].x, a0);
                a1 = fmaf(S[4*j+1], w4[j].y, a1);
                a2 = fmaf(S[4*j+2], w4[j].z, a2);
                a3 = fmaf(S[4*j+3], w4[j].w, a3);
            }
            float cs = -beta * ((a0 + a1) + (a2 + a3));
#pragma unroll
            for (int j = 0; j < 8; ++j) {
                float4 v4 = v4p[j];
                S[4*j+0] = fmaf(cs, w4[j].x, fmaf(k, v4.x, S[4*j+0]));
                S[4*j+1] = fmaf(cs, w4[j].y, fmaf(k, v4.y, S[4*j+1]));
                S[4*j+2] = fmaf(cs, w4[j].z, fmaf(k, v4.z, S[4*j+2]));
                S[4*j+3] = fmaf(cs, w4[j].w, fmaf(k, v4.w, S[4*j+3]));
            }
#pragma unroll
            for (int j = 0; j < 8; ++j) {
                *(float4*)&part[wid][lane][4*j] =
                    make_float4(q * S[4*j], q * S[4*j+1], q * S[4*j+2], q * S[4*j+3]);
            }
            __syncwarp();
            float o0 = 0.f, o1 = 0.f, o2 = 0.f, o3 = 0.f;
#pragma unroll
            for (int dd = 0; dd < 32; dd += 4) {
                o0 += part[wid][dd+0][lane];
                o1 += part[wid][dd+1][lane];
                o2 += part[wid][dd+2][lane];
                o3 += part[wid][dd+3][lane];
            }
            float o = (o0 + o1) + (o2 + o3);
            size_t oidx = (size_t)(rowbase + w * 8 + t) * 256 + h * 32 + lane;
            __nv_bfloat16 hi, lo;
            bf16split(o, hi, lo);
            g_atth[oidx] = hi; g_attl[oidx] = lo;
            __syncwarp();
        }
        if (w < 6) {
            __syncwarp();
            issue(w + 2, cur);
            asm volatile("cp.async.wait_group 1;" ::: "memory");
            __syncwarp();
        } else if (w == 6) {
            asm volatile("cp.async.wait_group 0;" ::: "memory");
            __syncwarp();
        }
    }
}

// -------------------- launch --------------------
extern "C" void kernel_launch(void* const* d_in, const int* in_sizes, int n_in,
                              void* d_out, int out_size) {
    const float* x     = (const float*)d_in[0];
    const float* Wq    = (const float*)d_in[1];
    const float* Wk    = (const float*)d_in[2];
    const float* Wv    = (const float*)d_in[3];
    const float* Ww    = (const float*)d_in[4];
    const float* Wbeta = (const float*)d_in[5];
    const float* bbeta = (const float*)d_in[6];
    const float* Wg    = (const float*)d_in[7];
    const float* bg    = (const float*)d_in[8];
    const float* Wo    = (const float*)d_in[9];
    float* out = (float*)d_out;

    void *pY, *pXh, *pXl, *pWh, *pWl, *pAh, *pAl, *pWoh, *pWol;
    cudaGetSymbolAddress(&pY,   g_Y);
    cudaGetSymbolAddress(&pXh,  g_xh);
    cudaGetSymbolAddress(&pXl,  g_xl);
    cudaGetSymbolAddress(&pWh,  g_Wh);
    cudaGetSymbolAddress(&pWl,  g_Wl);
    cudaGetSymbolAddress(&pAh,  g_atth);
    cudaGetSymbolAddress(&pAl,  g_attl);
    cudaGetSymbolAddress(&pWoh, g_woh);
    cudaGetSymbolAddress(&pWol, g_wol);

    const int SMEM = 3 * 4 * 128 * 32 * 2;   // 98304 bytes (3 swizzled 32KB stages)
    cudaFuncSetAttribute(hgemm3, cudaFuncAttributeMaxDynamicSharedMemorySize, SMEM);
    const int SCAN_SMEM = (8192 + WPB*32*36 + WPB*2*8) * 4;   // 51456 bytes
    cudaFuncSetAttribute(scanOut, cudaFuncAttributeMaxDynamicSharedMemorySize, SCAN_SMEM);

    // 1) pack + split weights; split x
    packW2<<<(NC * HIDq + 255) / 256, 256>>>(Wq, Wk, Wv, Ww, Wbeta, Wg);
    cvtA<<<(MROWS * HIDq / 4) / 256, 256>>>(x);
    cvtWo<<<(HIDq * 256 + 255) / 256, 256>>>(Wo);

    // 2) fused projection GEMM + activations: Y[16384,1040] = x @ W^T (tensor cores)
    hgemm3<<<dim3(NCP / 128, MROWS / 128), 256, SMEM>>>(
        (const __nv_bfloat16*)pXh, (const __nv_bfloat16*)pXl,
        (const __nv_bfloat16*)pWh, (const __nv_bfloat16*)pWl,
        (float*)pY, MROWS, NC, HIDq, 1, bbeta, bg);

    // 3) normalize w, fold scales, pack SoA recurrence streams
    prep<<<16384, 256>>>();

    // 4) chunked associative scan over the recurrence
    scanPA<<<(BH * CCH) / WPB, WPB * 32>>>();
    combine<<<BH, 1024>>>();
    scanOut<<<(BH * CCH) / WPB, WPB * 32, SCAN_SMEM>>>();

    // 5) output projection: out[16384,512] = att @ Wo^T (tensor cores)
    hgemm3<<<dim3(HIDq / 128, MROWS / 128), 256, SMEM>>>(
        (const __nv_bfloat16*)pAh, (const __nv_bfloat16*)pAl,
        (const __nv_bfloat16*)pWoh, (const __nv_bfloat16*)pWol,
        out, MROWS, HIDq, Hh * Dd, 0, nullptr, nullptr);
}

// round 13
// speedup vs baseline: 1.1504x; 1.0053x over previous
#include <cuda_runtime.h>
#include <cuda_bf16.h>
#include <cstdint>
#include <math.h>

// Problem constants
#define Bq   4
#define Tq   4096
#define Hh   8
#define Dd   32
#define HIDq 512
#define NC   1040            // packed projection columns: q256 k256 v256 w256 beta8 g8
#define NCP  1152            // NC padded to multiple of 128
#define MROWS (Bq*Tq)        // 16384
#define BH   (Bq*Hh)         // 32
#define CCH  64              // chunks
#define LCH  64              // steps per chunk
#define WPB  4               // warps per block in scan kernels

// -------------------- scratch (device globals; zero-initialized, no allocation) ----
__device__ float          g_Y[(size_t)MROWS * NC];        // projection output (68 MB)
__device__ __nv_bfloat16  g_Wh[(size_t)NCP * HIDq];       // packed weights hi (pad rows zero)
__device__ __nv_bfloat16  g_Wl[(size_t)NCP * HIDq];       // packed weights lo
__device__ __nv_bfloat16  g_xh[(size_t)MROWS * HIDq];     // x hi (16 MB)
__device__ __nv_bfloat16  g_xl[(size_t)MROWS * HIDq];     // x lo
__device__ __nv_bfloat16  g_woh[(size_t)HIDq * 256];      // Wo hi
__device__ __nv_bfloat16  g_wol[(size_t)HIDq * 256];      // Wo lo
__device__ __nv_bfloat16  g_atth[(size_t)MROWS * 256];    // attention out hi (8 MB)
__device__ __nv_bfloat16  g_attl[(size_t)MROWS * 256];    // attention out lo
__device__ float  g_w[(size_t)BH * Tq * Dd];              // normalized w (SoA streams)
__device__ float  g_v[(size_t)BH * Tq * Dd];
__device__ float  g_k[(size_t)BH * Tq * Dd];
__device__ float  g_q[(size_t)BH * Tq * Dd];              // q*scale*eg
__device__ float  g_beta[(size_t)BH * Tq];                // beta
__device__ float  g_P [(size_t)BH * CCH * 1024];          // chunk transfer matrices
__device__ float  g_A [(size_t)BH * CCH * 1024];          // chunk injections
__device__ float  g_S0[(size_t)BH * CCH * 1024];          // state at chunk starts

// -------------------- helpers --------------------
__device__ __forceinline__ void bf16split(float v, __nv_bfloat16& hi, __nv_bfloat16& lo) {
    hi = __float2bfloat16(v);
    lo = __float2bfloat16(v - __bfloat162float(hi));
}

__device__ __forceinline__ void ldsm4(uint32_t& r0, uint32_t& r1, uint32_t& r2, uint32_t& r3,
                                      uint32_t addr) {
    asm volatile("ldmatrix.sync.aligned.m8n8.x4.shared.b16 {%0,%1,%2,%3}, [%4];"
        : "=r"(r0), "=r"(r1), "=r"(r2), "=r"(r3) : "r"(addr));
}

__device__ __forceinline__ void mma_bf16(float* d, uint32_t a0, uint32_t a1, uint32_t a2,
                                         uint32_t a3, uint32_t b0, uint32_t b1) {
    asm volatile("mma.sync.aligned.m16n8k16.row.col.f32.bf16.bf16.f32 "
        "{%0,%1,%2,%3}, {%4,%5,%6,%7}, {%8,%9}, {%0,%1,%2,%3};"
        : "+f"(d[0]), "+f"(d[1]), "+f"(d[2]), "+f"(d[3])
        : "r"(a0), "r"(a1), "r"(a2), "r"(a3), "r"(b0), "r"(b1));
}

// swizzled smem byte offset within one 128x32 bf16 array: row stride 64B, 4 chunks of 16B
__device__ __forceinline__ uint32_t swz(int row, int col) {
    uint32_t chunk = (uint32_t)(col >> 3);
    return (uint32_t)(row * 64) + ((chunk ^ (((uint32_t)row >> 1) & 3u)) << 4);
}

__device__ __forceinline__ uint32_t s2u(const void* p) {
    return (uint32_t)__cvta_generic_to_shared(p);
}

// -------------------- weight packing + bf16 split --------------------
__global__ void packW2(const float* __restrict__ wq, const float* __restrict__ wk,
                       const float* __restrict__ wv, const float* __restrict__ ww,
                       const float* __restrict__ wb, const float* __restrict__ wg) {
    int i = blockIdx.x * 256 + threadIdx.x;
    if (i >= NC * HIDq) return;
    int r = i / HIDq, c = i % HIDq;
    float v;
    if      (r < 256)  v = wq[i];
    else if (r < 512)  v = wk[(r - 256)  * HIDq + c];
    else if (r < 768)  v = wv[(r - 512)  * HIDq + c];
    else if (r < 1024) v = ww[(r - 768)  * HIDq + c];
    else if (r < 1032) v = wb[(r - 1024) * HIDq + c];
    else               v = wg[(r - 1032) * HIDq + c];
    __nv_bfloat16 hi, lo;
    bf16split(v, hi, lo);
    g_Wh[i] = hi; g_Wl[i] = lo;
}

// -------------------- x -> bf16 hi/lo --------------------
__global__ void cvtA(const float* __restrict__ x) {
    int i = blockIdx.x * 256 + threadIdx.x;      // float4 index
    float4 v = ((const float4*)x)[i];
    __nv_bfloat16 h0, l0, h1, l1, h2, l2, h3, l3;
    bf16split(v.x, h0, l0); bf16split(v.y, h1, l1);
    bf16split(v.z, h2, l2); bf16split(v.w, h3, l3);
    ((__nv_bfloat162*)g_xh)[2*i]   = __halves2bfloat162(h0, h1);
    ((__nv_bfloat162*)g_xh)[2*i+1] = __halves2bfloat162(h2, h3);
    ((__nv_bfloat162*)g_xl)[2*i]   = __halves2bfloat162(l0, l1);
    ((__nv_bfloat162*)g_xl)[2*i+1] = __halves2bfloat162(l2, l3);
}

// -------------------- Wo -> bf16 hi/lo --------------------
__global__ void cvtWo(const float* __restrict__ Wo) {
    int i = blockIdx.x * 256 + threadIdx.x;
    if (i >= HIDq * 256) return;
    __nv_bfloat16 hi, lo;
    bf16split(Wo[i], hi, lo);
    g_woh[i] = hi; g_wol[i] = lo;
}

// -------------------- tensor-core GEMM: C[M,Nreal] = A[M,K] * B[N,K]^T --------------
// 3-term bf16 split, 128x128x32 tiles, 8 warps, 64x32 warp tiles, 3-stage swizzled
// cp.async ring, 2 CTAs/SM. SINGLE barrier per K-iteration: loads for stage it+2 are
// issued AFTER the barrier, so the top barrier also protects stage reuse.
__global__ void __launch_bounds__(256, 2)
hgemm3(const __nv_bfloat16* __restrict__ Ahp, const __nv_bfloat16* __restrict__ Alp,
       const __nv_bfloat16* __restrict__ Bhp, const __nv_bfloat16* __restrict__ Blp,
       float* __restrict__ C, int M, int Nreal, int K, int epi,
       const float* __restrict__ bbeta, const float* __restrict__ bg) {
    extern __shared__ __nv_bfloat16 smem[];   // 3 stages * 4 arrays * 128*32 bf16 = 96KB
    const int tid  = threadIdx.x;
    const int wid  = tid >> 5, lane = tid & 31;
    const int m0 = blockIdx.y * 128, n0 = blockIdx.x * 128;
    const int wm = (wid >> 2) * 64, wn = (wid & 3) * 32;
    const uint32_t sbase = s2u(&smem[0]);

    const __nv_bfloat16* gsrc[4];
    gsrc[0] = Ahp + (size_t)m0 * K;
    gsrc[1] = Alp + (size_t)m0 * K;
    gsrc[2] = Bhp + (size_t)n0 * K;
    gsrc[3] = Blp + (size_t)n0 * K;

    float acc[4][4][4];
#pragma unroll
    for (int mi = 0; mi < 4; ++mi)
#pragma unroll
        for (int nj = 0; nj < 4; ++nj)
#pragma unroll
            for (int cc = 0; cc < 4; ++cc) acc[mi][nj][cc] = 0.f;

    auto load_stage = [&](int s, int kt) {
#pragma unroll
        for (int arr = 0; arr < 4; ++arr) {
            uint32_t abase = sbase + (uint32_t)s * 32768u + (uint32_t)arr * 8192u;
            const __nv_bfloat16* src = gsrc[arr];
#pragma unroll
            for (int i = 0; i < 2; ++i) {
                int lin = i * 256 + tid;
                int r = lin >> 2, c = lin & 3;
                uint32_t dst = abase + swz(r, c * 8);
                const void* sp = src + (size_t)r * K + kt + c * 8;
                asm volatile("cp.async.cg.shared.global [%0], [%1], 16;" :: "r"(dst), "l"(sp));
            }
        }
        asm volatile("cp.async.commit_group;");
    };

    const int KT = K / 32;
    load_stage(0, 0);
    if (KT > 1) load_stage(1, 32);

    for (int it = 0; it < KT; ++it) {
        if (it + 1 < KT) {
            asm volatile("cp.async.wait_group 1;");
        } else {
            asm volatile("cp.async.wait_group 0;");
        }
        __syncthreads();   // single barrier: stage it%3 visible AND iter it-1 reads done
        if (it + 2 < KT) load_stage((it + 2) % 3, (it + 2) * 32);

        const uint32_t stg = sbase + (uint32_t)(it % 3) * 32768u;
        const uint32_t aHs = stg;
        const uint32_t aLs = stg + 8192u;
        const uint32_t bHs = stg + 16384u;
        const uint32_t bLs = stg + 24576u;

#pragma unroll
        for (int kk = 0; kk < 32; kk += 16) {
            uint32_t fbh[4][2], fbl[4][2];
#pragma unroll
            for (int j = 0; j < 2; ++j) {
                int row = wn + j * 16 + (lane & 7) + ((lane >> 4) & 1) * 8;
                int col = kk + ((lane >> 3) & 1) * 8;
                uint32_t off = swz(row, col);
                uint32_t t0, t1, t2, t3;
                ldsm4(t0, t1, t2, t3, bHs + off);
                fbh[j*2][0] = t0; fbh[j*2][1] = t1; fbh[j*2+1][0] = t2; fbh[j*2+1][1] = t3;
                ldsm4(t0, t1, t2, t3, bLs + off);
                fbl[j*2][0] = t0; fbl[j*2][1] = t1; fbl[j*2+1][0] = t2; fbl[j*2+1][1] = t3;
            }
#pragma unroll
            for (int mi = 0; mi < 4; ++mi) {
                int row = wm + mi * 16 + (lane & 7) + ((lane >> 3) & 1) * 8;
                int col = kk + ((lane >> 4) & 1) * 8;
                uint32_t off = swz(row, col);
                uint32_t ah0, ah1, ah2, ah3, al0, al1, al2, al3;
                ldsm4(ah0, ah1, ah2, ah3, aHs + off);
                ldsm4(al0, al1, al2, al3, aLs + off);
#pragma unroll
                for (int nj = 0; nj < 4; ++nj)
                    mma_bf16(acc[mi][nj], ah0, ah1, ah2, ah3, fbh[nj][0], fbh[nj][1]);
#pragma unroll
                for (int nj = 0; nj < 4; ++nj)
                    mma_bf16(acc[mi][nj], ah0, ah1, ah2, ah3, fbl[nj][0], fbl[nj][1]);
#pragma unroll
                for (int nj = 0; nj < 4; ++nj)
                    mma_bf16(acc[mi][nj], al0, al1, al2, al3, fbh[nj][0], fbh[nj][1]);
            }
        }
    }

    const int grp = lane >> 2, t2c = (lane & 3) << 1;
#pragma unroll
    for (int mi = 0; mi < 4; ++mi) {
#pragma unroll
        for (int nj = 0; nj < 4; ++nj) {
            int gm = m0 + wm + mi * 16 + grp;
            int gn = n0 + wn + nj * 8 + t2c;
            if (gn < Nreal) {
                float v0 = acc[mi][nj][0], v1 = acc[mi][nj][1];
                float v2 = acc[mi][nj][2], v3 = acc[mi][nj][3];
                if (epi && gn >= 1024) {
                    if (gn < 1032) {
                        v0 = 2.f / (1.f + expf(-(v0 + bbeta[gn - 1024])));
                        v1 = 2.f / (1.f + expf(-(v1 + bbeta[gn - 1023])));
                        v2 = 2.f / (1.f + expf(-(v2 + bbeta[gn - 1024])));
                        v3 = 2.f / (1.f + expf(-(v3 + bbeta[gn - 1023])));
                    } else {
                        v0 = 1.f / (1.f + expf(-(v0 + bg[gn - 1032])));
                        v1 = 1.f / (1.f + expf(-(v1 + bg[gn - 1031])));
                        v2 = 1.f / (1.f + expf(-(v2 + bg[gn - 1032])));
                        v3 = 1.f / (1.f + expf(-(v3 + bg[gn - 1031])));
                    }
                }
                float* p0 = C + (size_t)gm * Nreal + gn;
                float* p1 = C + (size_t)(gm + 8) * Nreal + gn;
                p0[0] = v0; p0[1] = v1;
                p1[0] = v2; p1[1] = v3;
            }
        }
    }
}

// -------------------- prep: normalize w, fold q*scale*eg, SoA streams ---------------
__global__ void __launch_bounds__(256) prep() {
    const float scale = 0.17677669529663687f;   // 32^-0.5
    int g    = blockIdx.x * 8 + (threadIdx.x >> 5);
    int lane = threadIdx.x & 31;
    int bh = g >> 12;
    int t  = g & 4095;
    int b = bh >> 3, h = bh & 7;
    const float* r = g_Y + (size_t)(b * Tq + t) * NC;

    float w = r[768 + h * 32 + lane];
    float ss = w * w;
    ss += __shfl_xor_sync(0xffffffffu, ss, 16);
    ss += __shfl_xor_sync(0xffffffffu, ss, 8);
    ss += __shfl_xor_sync(0xffffffffu, ss, 4);
    ss += __shfl_xor_sync(0xffffffffu, ss, 2);
    ss += __shfl_xor_sync(0xffffffffu, ss, 1);
    w = w / (sqrtf(ss) + 1e-6f);

    float v    = r[512 + h * 32 + lane];
    float k    = r[256 + h * 32 + lane];
    float q    = r[       h * 32 + lane];
    float beta = r[1024 + h];
    float eg   = r[1032 + h];   // sigmoid(zg) == exp(log_sigmoid(zg))

    size_t o = (size_t)g * 32 + lane;
    g_w[o] = w; g_v[o] = v; g_k[o] = k; g_q[o] = q * scale * eg;
    if (lane == 0) g_beta[g] = beta;
}

// -------------------- pass1: per-chunk transfer matrix P and injection A --------------------
__global__ void __launch_bounds__(WPB*32) scanPA() {
    __shared__ float wbuf[WPB][2][8][32];
    __shared__ float vbuf[WPB][2][8][32];
    __shared__ float kbuf[WPB][2][8][32];
    __shared__ float bbuf[WPB][2][8];

    const int wid  = threadIdx.x >> 5;
    const int lane = threadIdx.x & 31;
    const int wg   = blockIdx.x * WPB + wid;
    const int bh   = wg >> 6;
    const int c    = wg & 63;
    const size_t sbase = ((size_t)bh * Tq + (size_t)c * LCH) * 32;
    const size_t bbase = (size_t)bh * Tq + (size_t)c * LCH;

    auto issue = [&](int wnd, int bf) {
        size_t goff = sbase + (size_t)wnd * 256;
        uint32_t dw = s2u(&wbuf[wid][bf][0][0]);
        uint32_t dv = s2u(&vbuf[wid][bf][0][0]);
        uint32_t dk = s2u(&kbuf[wid][bf][0][0]);
#pragma unroll
        for (int i = 0; i < 2; ++i) {
            int e4 = i * 32 + lane;
            const void* sw = (const float4*)(g_w + goff) + e4;
            const void* sv = (const float4*)(g_v + goff) + e4;
            const void* sk = (const float4*)(g_k + goff) + e4;
            asm volatile("cp.async.cg.shared.global [%0], [%1], 16;" :: "r"(dw + e4*16u), "l"(sw));
            asm volatile("cp.async.cg.shared.global [%0], [%1], 16;" :: "r"(dv + e4*16u), "l"(sv));
            asm volatile("cp.async.cg.shared.global [%0], [%1], 16;" :: "r"(dk + e4*16u), "l"(sk));
        }
        if (lane < 8) {
            uint32_t db = s2u(&bbuf[wid][bf][lane]);
            asm volatile("cp.async.ca.shared.global [%0], [%1], 4;"
                         :: "r"(db), "l"(g_beta + bbase + wnd * 8 + lane));
        }
        asm volatile("cp.async.commit_group;");
    };

    issue(0, 0);
    issue(1, 1);
    asm volatile("cp.async.wait_group 1;" ::: "memory");
    __syncwarp();

    float P[32], A[32];
#pragma unroll
    for (int m = 0; m < 32; ++m) { P[m] = (m == lane) ? 1.f : 0.f; A[m] = 0.f; }

    for (int w = 0; w < 8; ++w) {
        const int cur = w & 1;
#pragma unroll
        for (int t = 0; t < 8; ++t) {
            const float4* w4p = (const float4*)&wbuf[wid][cur][t][0];
            const float4* v4p = (const float4*)&vbuf[wid][cur][t][0];
            float k    = kbuf[wid][cur][t][lane];
            float beta = bbuf[wid][cur][t];
            float p0 = 0.f, p1 = 0.f, p2 = 0.f, p3 = 0.f;
            float a0 = 0.f, a1 = 0.f, a2 = 0.f, a3 = 0.f;
            float4 w4[8];
#pragma unroll
            for (int j = 0; j < 8; ++j) {
                w4[j] = w4p[j];
                p0 = fmaf(P[4*j+0], w4[j].x, p0);
                p1 = fmaf(P[4*j+1], w4[j].y, p1);
                p2 = fmaf(P[4*j+2], w4[j].z, p2);
                p3 = fmaf(P[4*j+3], w4[j].w, p3);
                a0 = fmaf(A[4*j+0], w4[j].x, a0);
                a1 = fmaf(A[4*j+1], w4[j].y, a1);
                a2 = fmaf(A[4*j+2], w4[j].z, a2);
                a3 = fmaf(A[4*j+3], w4[j].w, a3);
            }
            float cp = -beta * ((p0 + p1) + (p2 + p3));
            float ca = -beta * ((a0 + a1) + (a2 + a3));
#pragma unroll
            for (int j = 0; j < 8; ++j) {
                float4 v4 = v4p[j];
                P[4*j+0] = fmaf(cp, w4[j].x, P[4*j+0]);
                P[4*j+1] = fmaf(cp, w4[j].y, P[4*j+1]);
                P[4*j+2] = fmaf(cp, w4[j].z, P[4*j+2]);
                P[4*j+3] = fmaf(cp, w4[j].w, P[4*j+3]);
                A[4*j+0] = fmaf(ca, w4[j].x, fmaf(k, v4.x, A[4*j+0]));
                A[4*j+1] = fmaf(ca, w4[j].y, fmaf(k, v4.y, A[4*j+1]));
                A[4*j+2] = fmaf(ca, w4[j].z, fmaf(k, v4.z, A[4*j+2]));
                A[4*j+3] = fmaf(ca, w4[j].w, fmaf(k, v4.w, A[4*j+3]));
            }
        }
        if (w < 6) {
            __syncwarp();
            issue(w + 2, cur);
            asm volatile("cp.async.wait_group 1;" ::: "memory");
            __syncwarp();
        } else if (w == 6) {
            asm volatile("cp.async.wait_group 0;" ::: "memory");
            __syncwarp();
        }
    }

    size_t obase = ((size_t)bh * CCH + c) * 1024 + (size_t)lane * 32;
#pragma unroll
    for (int j = 0; j < 8; ++j) {
        *(float4*)&g_P[obase + 4*j] = make_float4(P[4*j], P[4*j+1], P[4*j+2], P[4*j+3]);
        *(float4*)&g_A[obase + 4*j] = make_float4(A[4*j], A[4*j+1], A[4*j+2], A[4*j+3]);
    }
}

// -------------------- combine: sequential chunk-boundary states --------------------
__global__ void __launch_bounds__(1024, 1) combine() {
    __shared__ float Ssh[32][32];
    const int bh = blockIdx.x;
    const int tid = threadIdx.x;
    const int d = tid >> 5, m = tid & 31;

    float s = 0.f;
    for (int c = 0; c < CCH; ++c) {
        size_t base = ((size_t)bh * CCH + c) * 1024;
        g_S0[base + tid] = s;
        Ssh[d][m] = s;
        __syncthreads();
        float acc = g_A[base + tid];
        const float* Pc = g_P + base;
#pragma unroll
        for (int mm = 0; mm < 32; ++mm)
            acc = fmaf(Ssh[d][mm], Pc[mm * 32 + m], acc);
        __syncthreads();
        s = acc;
    }
}

// -------------------- pass2: replay chunks, emit outputs as bf16 hi/lo ----------------
__global__ void __launch_bounds__(WPB*32) scanOut() {
    extern __shared__ float dyn[];
    float (*wbuf)[2][8][32] = (float(*)[2][8][32])(dyn);
    float (*vbuf)[2][8][32] = (float(*)[2][8][32])(dyn + 2048);
    float (*kbuf)[2][8][32] = (float(*)[2][8][32])(dyn + 4096);
    float (*qbuf)[2][8][32] = (float(*)[2][8][32])(dyn + 6144);
    float (*part)[32][36]   = (float(*)[32][36])(dyn + 8192);
    float (*bbuf)[2][8]     = (float(*)[2][8])(dyn + 8192 + WPB*32*36);

    const int wid  = threadIdx.x >> 5;
    const int lane = threadIdx.x & 31;
    const int wg   = blockIdx.x * WPB + wid;
    const int bh   = wg >> 6;
    const int c    = wg & 63;
    const int b = bh >> 3, h = bh & 7;
    const size_t sbase = ((size_t)bh * Tq + (size_t)c * LCH) * 32;
    const size_t bbase = (size_t)bh * Tq + (size_t)c * LCH;
    const size_t s0base = ((size_t)bh * CCH + c) * 1024 + (size_t)lane * 32;
    const int rowbase = b * Tq + c * LCH;

    auto issue = [&](int wnd, int bf) {
        size_t goff = sbase + (size_t)wnd * 256;
        uint32_t dw = s2u(&wbuf[wid][bf][0][0]);
        uint32_t dv = s2u(&vbuf[wid][bf][0][0]);
        uint32_t dk = s2u(&kbuf[wid][bf][0][0]);
        uint32_t dq = s2u(&qbuf[wid][bf][0][0]);
#pragma unroll
        for (int i = 0; i < 2; ++i) {
            int e4 = i * 32 + lane;
            asm volatile("cp.async.cg.shared.global [%0], [%1], 16;"
                         :: "r"(dw + e4*16u), "l"((const float4*)(g_w + goff) + e4));
            asm volatile("cp.async.cg.shared.global [%0], [%1], 16;"
                         :: "r"(dv + e4*16u), "l"((const float4*)(g_v + goff) + e4));
            asm volatile("cp.async.cg.shared.global [%0], [%1], 16;"
                         :: "r"(dk + e4*16u), "l"((const float4*)(g_k + goff) + e4));
            asm volatile("cp.async.cg.shared.global [%0], [%1], 16;"
                         :: "r"(dq + e4*16u), "l"((const float4*)(g_q + goff) + e4));
        }
        if (lane < 8) {
            uint32_t db = s2u(&bbuf[wid][bf][lane]);
            asm volatile("cp.async.ca.shared.global [%0], [%1], 4;"
                         :: "r"(db), "l"(g_beta + bbase + wnd * 8 + lane));
        }
        asm volatile("cp.async.commit_group;");
    };

    issue(0, 0);
    issue(1, 1);
    asm volatile("cp.async.wait_group 1;" ::: "memory");
    __syncwarp();

    float S[32];
#pragma unroll
    for (int j = 0; j < 8; ++j) {
        float4 s0 = *(const float4*)&g_S0[s0base + 4*j];
        S[4*j] = s0.x; S[4*j+1] = s0.y; S[4*j+2] = s0.z; S[4*j+3] = s0.w;
    }

    for (int w = 0; w < 8; ++w) {
        const int cur = w & 1;
#pragma unroll
        for (int t = 0; t < 8; ++t) {
            const float4* w4p = (const float4*)&wbuf[wid][cur][t][0];
            const float4* v4p = (const float4*)&vbuf[wid][cur][t][0];
            float k    = kbuf[wid][cur][t][lane];
            float q    = qbuf[wid][cur][t][lane];
            float beta = bbuf[wid][cur][t];
            float a0 = 0.f, a1 = 0.f, a2 = 0.f, a3 = 0.f;
            float4 w4[8];
#pragma unroll
            for (int j = 0; j < 8; ++j) {
                w4[j] = w4p[j];
                a0 = fmaf(S[4*j+0], w4[j].x, a0);
                a1 = fmaf(S[4*j+1], w4[j].y, a1);
                a2 = fmaf(S[4*j+2], w4[j].z, a2);
                a3 = fmaf(S[4*j+3], w4[j].w, a3);
            }
            float cs = -beta * ((a0 + a1) + (a2 + a3));
#pragma unroll
            for (int j = 0; j < 8; ++j) {
                float4 v4 = v4p[j];
                S[4*j+0] = fmaf(cs, w4[j].x, fmaf(k, v4.x, S[4*j+0]));
                S[4*j+1] = fmaf(cs, w4[j].y, fmaf(k, v4.y, S[4*j+1]));
                S[4*j+2] = fmaf(cs, w4[j].z, fmaf(k, v4.z, S[4*j+2]));
                S[4*j+3] = fmaf(cs, w4[j].w, fmaf(k, v4.w, S[4*j+3]));
            }
#pragma unroll
            for (int j = 0; j < 8; ++j) {
                *(float4*)&part[wid][lane][4*j] =
                    make_float4(q * S[4*j], q * S[4*j+1], q * S[4*j+2], q * S[4*j+3]);
            }
            __syncwarp();
            float o0 = 0.f, o1 = 0.f, o2 = 0.f, o3 = 0.f;
#pragma unroll
            for (int dd = 0; dd < 32; dd += 4) {
                o0 += part[wid][dd+0][lane];
                o1 += part[wid][dd+1][lane];
                o2 += part[wid][dd+2][lane];
                o3 += part[wid][dd+3][lane];
            }
            float o = (o0 + o1) + (o2 + o3);
            size_t oidx = (size_t)(rowbase + w * 8 + t) * 256 + h * 32 + lane;
            __nv_bfloat16 hi, lo;
            bf16split(o, hi, lo);
            g_atth[oidx] = hi; g_attl[oidx] = lo;
            __syncwarp();
        }
        if (w < 6) {
            __syncwarp();
            issue(w + 2, cur);
            asm volatile("cp.async.wait_group 1;" ::: "memory");
            __syncwarp();
        } else if (w == 6) {
            asm volatile("cp.async.wait_group 0;" ::: "memory");
            __syncwarp();
        }
    }
}

// -------------------- launch --------------------
extern "C" void kernel_launch(void* const* d_in, const int* in_sizes, int n_in,
                              void* d_out, int out_size) {
    const float* x     = (const float*)d_in[0];
    const float* Wq    = (const float*)d_in[1];
    const float* Wk    = (const float*)d_in[2];
    const float* Wv    = (const float*)d_in[3];
    const float* Ww    = (const float*)d_in[4];
    const float* Wbeta = (const float*)d_in[5];
    const float* bbeta = (const float*)d_in[6];
    const float* Wg    = (const float*)d_in[7];
    const float* bg    = (const float*)d_in[8];
    const float* Wo    = (const float*)d_in[9];
    float* out = (float*)d_out;

    void *pY, *pXh, *pXl, *pWh, *pWl, *pAh, *pAl, *pWoh, *pWol;
    cudaGetSymbolAddress(&pY,   g_Y);
    cudaGetSymbolAddress(&pXh,  g_xh);
    cudaGetSymbolAddress(&pXl,  g_xl);
    cudaGetSymbolAddress(&pWh,  g_Wh);
    cudaGetSymbolAddress(&pWl,  g_Wl);
    cudaGetSymbolAddress(&pAh,  g_atth);
    cudaGetSymbolAddress(&pAl,  g_attl);
    cudaGetSymbolAddress(&pWoh, g_woh);
    cudaGetSymbolAddress(&pWol, g_wol);

    const int SMEM = 3 * 4 * 128 * 32 * 2;   // 98304 bytes (3 swizzled 32KB stages)
    cudaFuncSetAttribute(hgemm3, cudaFuncAttributeMaxDynamicSharedMemorySize, SMEM);
    const int SCAN_SMEM = (8192 + WPB*32*36 + WPB*2*8) * 4;   // 51456 bytes
    cudaFuncSetAttribute(scanOut, cudaFuncAttributeMaxDynamicSharedMemorySize, SCAN_SMEM);

    // 1) pack + split weights; split x
    packW2<<<(NC * HIDq + 255) / 256, 256>>>(Wq, Wk, Wv, Ww, Wbeta, Wg);
    cvtA<<<(MROWS * HIDq / 4) / 256, 256>>>(x);
    cvtWo<<<(HIDq * 256 + 255) / 256, 256>>>(Wo);

    // 2) fused projection GEMM + activations: Y[16384,1040] = x @ W^T (tensor cores)
    hgemm3<<<dim3(NCP / 128, MROWS / 128), 256, SMEM>>>(
        (const __nv_bfloat16*)pXh, (const __nv_bfloat16*)pXl,
        (const __nv_bfloat16*)pWh, (const __nv_bfloat16*)pWl,
        (float*)pY, MROWS, NC, HIDq, 1, bbeta, bg);

    // 3) normalize w, fold scales, pack SoA recurrence streams
    prep<<<16384, 256>>>();

    // 4) chunked associative scan over the recurrence
    scanPA<<<(BH * CCH) / WPB, WPB * 32>>>();
    combine<<<BH, 1024>>>();
    scanOut<<<(BH * CCH) / WPB, WPB * 32, SCAN_SMEM>>>();

    // 5) output projection: out[16384,512] = att @ Wo^T (tensor cores)
    hgemm3<<<dim3(HIDq / 128, MROWS / 128), 256, SMEM>>>(
        (const __nv_bfloat16*)pAh, (const __nv_bfloat16*)pAl,
        (const __nv_bfloat16*)pWoh, (const __nv_bfloat16*)pWol,
        out, MROWS, HIDq, Hh * Dd, 0, nullptr, nullptr);
}